// round 5
// baseline (speedup 1.0000x reference)
#include <cuda_runtime.h>
#include <cuda_fp16.h>
#include <math.h>
#include <stdint.h>

#define BATCH 4
#define NSEQ 2048
#define DIM 1024
#define HEADS 16
#define DH 64
#define INNER 1024
#define NQKV 3072
#define ROWS (BATCH*NSEQ)

// Scratch
__device__ __half g_xn_h[(size_t)ROWS * DIM];
__device__ float  g_qkv[(size_t)ROWS * NQKV];
__device__ __half g_o_h[(size_t)ROWS * INNER];
__device__ __half g_wqkvT_h[(size_t)NQKV * DIM];
__device__ __half g_woutT_h[(size_t)DIM * INNER];
__device__ float  g_cosT[(size_t)NSEQ * DH];
__device__ float  g_sinT[(size_t)NSEQ * DH];
// head-major hi/lo fp16 tensors: [b, h, n, 64]
__device__ __half g_q_hi[(size_t)ROWS * INNER];
__device__ __half g_q_lo[(size_t)ROWS * INNER];
__device__ __half g_k_hi[(size_t)ROWS * INNER];
__device__ __half g_k_lo[(size_t)ROWS * INNER];
__device__ __half g_v_hi[(size_t)ROWS * INNER];
__device__ __half g_v_lo[(size_t)ROWS * INNER];

__device__ __forceinline__ uint32_t smem_u32(const void* p) {
    uint32_t a;
    asm("{ .reg .u64 t; cvta.to.shared.u64 t, %1; cvt.u32.u64 %0, t; }"
        : "=r"(a) : "l"(p));
    return a;
}
__device__ __forceinline__ void cp_async16(uint32_t dst, const void* src) {
    asm volatile("cp.async.cg.shared.global [%0], [%1], 16;"
                 :: "r"(dst), "l"(src) : "memory");
}
__device__ __forceinline__ void ldsm4(uint32_t* r, uint32_t addr) {
    asm volatile("ldmatrix.sync.aligned.m8n8.x4.shared.b16 {%0,%1,%2,%3}, [%4];"
                 : "=r"(r[0]), "=r"(r[1]), "=r"(r[2]), "=r"(r[3]) : "r"(addr));
}
__device__ __forceinline__ void ldsm4t(uint32_t* r, uint32_t addr) {
    asm volatile("ldmatrix.sync.aligned.m8n8.x4.trans.shared.b16 {%0,%1,%2,%3}, [%4];"
                 : "=r"(r[0]), "=r"(r[1]), "=r"(r[2]), "=r"(r[3]) : "r"(addr));
}
__device__ __forceinline__ void mma16816(float* c, const uint32_t* a, uint32_t b0, uint32_t b1) {
    asm volatile(
        "mma.sync.aligned.m16n8k16.row.col.f32.f16.f16.f32 "
        "{%0,%1,%2,%3}, {%4,%5,%6,%7}, {%8,%9}, {%0,%1,%2,%3};"
        : "+f"(c[0]), "+f"(c[1]), "+f"(c[2]), "+f"(c[3])
        : "r"(a[0]), "r"(a[1]), "r"(a[2]), "r"(a[3]), "r"(b0), "r"(b1));
}
__device__ __forceinline__ float exp2p(float x) {
    x = fmaxf(x, -126.f);
    float t = x + 12582912.f;
    float fi = t - 12582912.f;
    float f = x - fi;
    float p = 1.3333558146e-3f;
    p = fmaf(p, f, 9.6181291076e-3f);
    p = fmaf(p, f, 5.5504108665e-2f);
    p = fmaf(p, f, 2.4022650696e-1f);
    p = fmaf(p, f, 6.9314718056e-1f);
    p = fmaf(p, f, 1.0f);
    int ei = (int)fi;
    return __int_as_float(__float_as_int(p) + (ei << 23));
}
__device__ __forceinline__ uint32_t pack_h2(__half a, __half b) {
    __half2 t = __halves2half2(a, b);
    return *reinterpret_cast<uint32_t*>(&t);
}
__device__ __forceinline__ void hilo2(float a, float b, uint32_t& hi, uint32_t& lo) {
    __half ha = __float2half_rn(a), hb = __float2half_rn(b);
    hi = pack_h2(ha, hb);
    lo = pack_h2(__float2half_rn(a - __half2float(ha)),
                 __float2half_rn(b - __half2float(hb)));
}
#define SWZ(r, g) ((uint32_t)((r) * 128 + (((g) ^ ((r) & 7)) * 16)))

// ---------------------------------------------------------------------------
// LayerNorm -> half
// ---------------------------------------------------------------------------
__global__ __launch_bounds__(256) void ln_kernel(
    const float* __restrict__ x, const float* __restrict__ gg,
    const float* __restrict__ bb, __half* __restrict__ out)
{
    int row = blockIdx.x;
    int tid = threadIdx.x;
    const float4* xr = (const float4*)(x + (size_t)row * DIM);
    float4 v = xr[tid];
    float s  = v.x + v.y + v.z + v.w;
    float s2 = fmaf(v.x, v.x, fmaf(v.y, v.y, fmaf(v.z, v.z, v.w * v.w)));
    #pragma unroll
    for (int o = 16; o; o >>= 1) {
        s  += __shfl_xor_sync(0xffffffffu, s, o);
        s2 += __shfl_xor_sync(0xffffffffu, s2, o);
    }
    __shared__ float rs[8], rs2[8];
    __shared__ float mu_s, rstd_s;
    int w = tid >> 5;
    if ((tid & 31) == 0) { rs[w] = s; rs2[w] = s2; }
    __syncthreads();
    if (tid == 0) {
        float a = 0.f, a2 = 0.f;
        #pragma unroll
        for (int i = 0; i < 8; i++) { a += rs[i]; a2 += rs2[i]; }
        float mu = a * (1.f / DIM);
        float var = a2 * (1.f / DIM) - mu * mu;
        mu_s = mu;
        rstd_s = rsqrtf(var + 1e-5f);
    }
    __syncthreads();
    float mu = mu_s, r = rstd_s;
    float4 g4 = ((const float4*)gg)[tid];
    float4 b4 = ((const float4*)bb)[tid];
    __half2* orow = (__half2*)(out + (size_t)row * DIM);
    orow[tid * 2]     = __floats2half2_rn((v.x - mu) * r * g4.x + b4.x,
                                          (v.y - mu) * r * g4.y + b4.y);
    orow[tid * 2 + 1] = __floats2half2_rn((v.z - mu) * r * g4.z + b4.z,
                                          (v.w - mu) * r * g4.w + b4.w);
}

__global__ __launch_bounds__(256) void transpose_cvt_kernel(
    const float* __restrict__ src, __half* __restrict__ dst, int K, int N)
{
    __shared__ float t[32][33];
    int n0 = blockIdx.x * 32, k0 = blockIdx.y * 32;
    int tx = threadIdx.x & 31, ty = threadIdx.x >> 5;
    #pragma unroll
    for (int i = 0; i < 4; i++)
        t[ty + 8 * i][tx] = src[(size_t)(k0 + ty + 8 * i) * N + n0 + tx];
    __syncthreads();
    #pragma unroll
    for (int i = 0; i < 4; i++)
        dst[(size_t)(n0 + ty + 8 * i) * K + k0 + tx] = __float2half(t[tx][ty + 8 * i]);
}

// ---------------------------------------------------------------------------
// HGEMM (as R4): C fp32 = A(h) @ BT(h)^T
// ---------------------------------------------------------------------------
__global__ __launch_bounds__(256) void hgemm(
    const __half* __restrict__ A, const __half* __restrict__ BT,
    const float* __restrict__ bias, float* __restrict__ C,
    int M, int N, int K, int has_bias)
{
    __shared__ __align__(128) char sm[32768];
    uint32_t sbase = smem_u32(sm);
    int tid = threadIdx.x, lane = tid & 31, wid = tid >> 5;
    int wm = (wid >> 2) * 64, wn = (wid & 3) * 32;
    int row0 = blockIdx.y * 128, col0 = blockIdx.x * 128;
    const __half* Ag = A  + (size_t)row0 * K;
    const __half* Bg = BT + (size_t)col0 * K;

    float acc[4][4][4];
    #pragma unroll
    for (int i = 0; i < 4; i++)
        #pragma unroll
        for (int j = 0; j < 4; j++)
            #pragma unroll
            for (int q = 0; q < 4; q++) acc[i][j][q] = 0.f;

    #define SWA(base, r, c) ((base) + (uint32_t)((r) * 64 + (((c) ^ (((r) >> 1) & 3)) * 16)))
    #define LOAD_STAGE(stage, k0)                                              \
    {                                                                          \
        uint32_t abase = sbase + (stage) * 8192;                               \
        uint32_t bbase = sbase + 16384 + (stage) * 8192;                       \
        _Pragma("unroll")                                                      \
        for (int t = 0; t < 2; t++) {                                          \
            int idx = tid + t * 256;                                           \
            int r = idx >> 2, c = idx & 3;                                     \
            cp_async16(SWA(abase, r, c), Ag + (size_t)r * K + (k0) + c * 8);   \
            cp_async16(SWA(bbase, r, c), Bg + (size_t)r * K + (k0) + c * 8);   \
        }                                                                      \
        asm volatile("cp.async.commit_group;" ::: "memory");                   \
    }

    LOAD_STAGE(0, 0);
    const int NK = K >> 5;
    for (int kt = 0; kt < NK; kt++) {
        int cur = kt & 1;
        if (kt + 1 < NK) {
            LOAD_STAGE(1 - cur, (kt + 1) << 5);
            asm volatile("cp.async.wait_group 1;" ::: "memory");
        } else {
            asm volatile("cp.async.wait_group 0;" ::: "memory");
        }
        __syncthreads();
        uint32_t abase = sbase + cur * 8192;
        uint32_t bbase = sbase + 16384 + cur * 8192;
        #pragma unroll
        for (int ks = 0; ks < 2; ks++) {
            uint32_t a[4][4], b[2][4];
            #pragma unroll
            for (int mf = 0; mf < 4; mf++) {
                int rr = wm + mf * 16 + ((lane >> 3) & 1) * 8 + (lane & 7);
                int cc = ks * 2 + (lane >> 4);
                ldsm4(a[mf], SWA(abase, rr, cc));
            }
            #pragma unroll
            for (int n2 = 0; n2 < 2; n2++) {
                int rr = wn + n2 * 16 + ((lane >> 4) & 1) * 8 + (lane & 7);
                int cc = ks * 2 + ((lane >> 3) & 1);
                ldsm4(b[n2], SWA(bbase, rr, cc));
            }
            #pragma unroll
            for (int mf = 0; mf < 4; mf++)
                #pragma unroll
                for (int nf = 0; nf < 4; nf++)
                    mma16816(acc[mf][nf], a[mf],
                             b[nf >> 1][(nf & 1) * 2], b[nf >> 1][(nf & 1) * 2 + 1]);
        }
        __syncthreads();
    }
    #pragma unroll
    for (int mf = 0; mf < 4; mf++) {
        int grow = row0 + wm + mf * 16 + (lane >> 2);
        #pragma unroll
        for (int nf = 0; nf < 4; nf++) {
            int gcol = col0 + wn + nf * 8 + (lane & 3) * 2;
            float bx = 0.f, by = 0.f;
            if (has_bias) {
                float2 bb = *(const float2*)(bias + gcol);
                bx = bb.x; by = bb.y;
            }
            *(float2*)(C + (size_t)grow * N + gcol) =
                make_float2(acc[mf][nf][0] + bx, acc[mf][nf][1] + by);
            *(float2*)(C + (size_t)(grow + 8) * N + gcol) =
                make_float2(acc[mf][nf][2] + bx, acc[mf][nf][3] + by);
        }
    }
}

// ---------------------------------------------------------------------------
// RoPE tables
// ---------------------------------------------------------------------------
__global__ __launch_bounds__(256) void rope_table_kernel(
    float* __restrict__ cosT, float* __restrict__ sinT)
{
    int idx = blockIdx.x * blockDim.x + threadIdx.x;
    int pos = idx >> 6, d = idx & 63;
    float fr = powf(10000.f, -(float)(d >> 1) * (1.f / 32.f));
    float a = (float)pos * fr;
    float s, c;
    sincosf(a, &s, &c);
    cosT[idx] = c;
    sinT[idx] = s;
}

// ---------------------------------------------------------------------------
// Fused RoPE + hi/lo fp16 split + [b,h,n,64] relayout.
// block 384: tid/128 = part (q,k,v); each thread does 8 contiguous d.
// ---------------------------------------------------------------------------
__global__ __launch_bounds__(384) void rope_cvt_kernel(
    const float* __restrict__ qkv,
    const float* __restrict__ cosT, const float* __restrict__ sinT,
    __half* __restrict__ q_hi, __half* __restrict__ q_lo,
    __half* __restrict__ k_hi, __half* __restrict__ k_lo,
    __half* __restrict__ v_hi, __half* __restrict__ v_lo)
{
    const float QSC = 0.125f * 1.44269504089f;
    int tid = threadIdx.x;
    int part = tid >> 7;            // 0=q 1=k 2=v
    int sub = tid & 127;
    int h = sub >> 3, g = sub & 7, d0 = g * 8;
    int row = blockIdx.x;
    int b = row >> 11, pos = row & (NSEQ - 1);

    const float* src = qkv + (size_t)row * NQKV + part * INNER + h * DH;
    float f[8];
    *(float4*)&f[0] = *(const float4*)(src + d0);
    *(float4*)&f[4] = *(const float4*)(src + d0 + 4);

    if (part < 2) {
        int d0p = d0 ^ 32;
        float pr[8];
        *(float4*)&pr[0] = *(const float4*)(src + d0p);
        *(float4*)&pr[4] = *(const float4*)(src + d0p + 4);
        float sgn = (d0 < 32) ? -1.f : 1.f;
        #pragma unroll
        for (int j = 0; j < 8; j++) {
            float c = cosT[pos * DH + d0 + j];
            float s = sinT[pos * DH + d0 + j];
            f[j] = f[j] * c + sgn * pr[j] * s;
        }
    }
    if (part == 0) {
        #pragma unroll
        for (int j = 0; j < 8; j++) f[j] *= QSC;
    }

    uint32_t ph[4], pl[4];
    #pragma unroll
    for (int i = 0; i < 4; i++) hilo2(f[2*i], f[2*i+1], ph[i], pl[i]);

    size_t off = ((size_t)(b * HEADS + h) * NSEQ + pos) * DH + d0;
    __half *dh, *dl;
    if (part == 0)      { dh = q_hi; dl = q_lo; }
    else if (part == 1) { dh = k_hi; dl = k_lo; }
    else                { dh = v_hi; dl = v_lo; }
    *(uint4*)(dh + off) = make_uint4(ph[0], ph[1], ph[2], ph[3]);
    *(uint4*)(dl + off) = make_uint4(pl[0], pl[1], pl[2], pl[3]);
}

// ---------------------------------------------------------------------------
// Flash attention v2: precomputed hi/lo fp16, cp.async double-buffered K/V.
// Block: 128 q-rows x head x batch, 8 warps, 64-key tiles.
// smem: Q (32KB) + 2 stages x 32KB = 96KB dynamic.
// ---------------------------------------------------------------------------
__global__ __launch_bounds__(256) void fa_kernel(
    const __half* __restrict__ q_hi, const __half* __restrict__ q_lo,
    const __half* __restrict__ k_hi, const __half* __restrict__ k_lo,
    const __half* __restrict__ v_hi, const __half* __restrict__ v_lo,
    __half* __restrict__ o)
{
    extern __shared__ __align__(128) char sm[];
    uint32_t sb = smem_u32(sm);
    const uint32_t QHI = 0, QLO = 16384, STG = 32768;
    // within a stage: KHI+0, KLO+8192, VHI+16384, VLO+24576

    int tid = threadIdx.x, lane = tid & 31, wid = tid >> 5;
    int qt = blockIdx.x, h = blockIdx.y, b = blockIdx.z;
    size_t hb = (size_t)(b * HEADS + h) * NSEQ;

    // ---- Q via cp.async: 2 arrays x 128 rows; thread -> one row of one array
    {
        int arr = tid >> 7, r = tid & 127;
        const __half* src = (arr ? q_lo : q_hi) + (hb + qt * 128 + r) * DH;
        uint32_t dst = sb + (arr ? QLO : QHI);
        #pragma unroll
        for (int g = 0; g < 8; g++)
            cp_async16(dst + SWZ(r, g), src + g * 8);
        asm volatile("cp.async.commit_group;" ::: "memory");
    }
    // ---- KV stage loader: 4 arrays x 64 rows; thread -> one row of one array
    const __half* kvsrc[4] = { k_hi + hb * DH, k_lo + hb * DH,
                               v_hi + hb * DH, v_lo + hb * DH };
    int kvarr = tid >> 6, kvr = tid & 63;
    const __half* kvbase = kvsrc[kvarr];
    #define LOAD_KV(buf, s0)                                                   \
    {                                                                          \
        uint32_t dst = sb + STG + (buf) * 32768 + kvarr * 8192;                \
        const __half* srcp = kvbase + ((size_t)(s0) + kvr) * DH;               \
        _Pragma("unroll")                                                      \
        for (int g = 0; g < 8; g++)                                            \
            cp_async16(dst + SWZ(kvr, g), srcp + g * 8);                       \
        asm volatile("cp.async.commit_group;" ::: "memory");                   \
    }

    LOAD_KV(0, 0);
    asm volatile("cp.async.wait_group 1;" ::: "memory");  // Q arrived
    __syncthreads();

    uint32_t qhi[4][4], qlo[4][4];
    #pragma unroll
    for (int kt = 0; kt < 4; kt++) {
        int rr = wid * 16 + ((lane >> 3) & 1) * 8 + (lane & 7);
        int gg = 2 * kt + (lane >> 4);
        ldsm4(qhi[kt], sb + QHI + SWZ(rr, gg));
        ldsm4(qlo[kt], sb + QLO + SWZ(rr, gg));
    }

    float accO[8][4];
    #pragma unroll
    for (int i = 0; i < 8; i++)
        #pragma unroll
        for (int j = 0; j < 4; j++) accO[i][j] = 0.f;
    float m0 = -1e30f, m1 = -1e30f, l0 = 0.f, l1 = 0.f;

    const int NT = NSEQ / 64;
    for (int kt = 0; kt < NT; kt++) {
        int cur = kt & 1;
        if (kt + 1 < NT) {
            LOAD_KV(1 - cur, (kt + 1) * 64);
            asm volatile("cp.async.wait_group 1;" ::: "memory");
        } else {
            asm volatile("cp.async.wait_group 0;" ::: "memory");
        }
        __syncthreads();
        uint32_t KHI = sb + STG + cur * 32768;
        uint32_t KLO = KHI + 8192, VHI = KHI + 16384, VLO = KHI + 24576;

        // ---- S = Q K^T (3-term compensated)
        float sAcc[8][4];
        #pragma unroll
        for (int i = 0; i < 8; i++)
            #pragma unroll
            for (int j = 0; j < 4; j++) sAcc[i][j] = 0.f;
        #pragma unroll
        for (int kk = 0; kk < 4; kk++) {
            #pragma unroll
            for (int g = 0; g < 4; g++) {
                uint32_t bh[4], bl[4];
                int rr = g * 16 + ((lane >> 4) & 1) * 8 + (lane & 7);
                int cc = kk * 2 + ((lane >> 3) & 1);
                ldsm4(bh, KHI + SWZ(rr, cc));
                ldsm4(bl, KLO + SWZ(rr, cc));
                mma16816(sAcc[2*g],   qhi[kk], bh[0], bh[1]);
                mma16816(sAcc[2*g+1], qhi[kk], bh[2], bh[3]);
                mma16816(sAcc[2*g],   qhi[kk], bl[0], bl[1]);
                mma16816(sAcc[2*g+1], qhi[kk], bl[2], bl[3]);
                mma16816(sAcc[2*g],   qlo[kk], bh[0], bh[1]);
                mma16816(sAcc[2*g+1], qlo[kk], bh[2], bh[3]);
            }
        }

        // ---- online softmax (FFMA exp2)
        float mx0 = -1e30f, mx1 = -1e30f;
        #pragma unroll
        for (int nt = 0; nt < 8; nt++) {
            mx0 = fmaxf(mx0, fmaxf(sAcc[nt][0], sAcc[nt][1]));
            mx1 = fmaxf(mx1, fmaxf(sAcc[nt][2], sAcc[nt][3]));
        }
        mx0 = fmaxf(mx0, __shfl_xor_sync(0xffffffffu, mx0, 1));
        mx0 = fmaxf(mx0, __shfl_xor_sync(0xffffffffu, mx0, 2));
        mx1 = fmaxf(mx1, __shfl_xor_sync(0xffffffffu, mx1, 1));
        mx1 = fmaxf(mx1, __shfl_xor_sync(0xffffffffu, mx1, 2));
        float mn0 = fmaxf(m0, mx0), mn1 = fmaxf(m1, mx1);
        float sc0 = exp2p(m0 - mn0), sc1 = exp2p(m1 - mn1);
        m0 = mn0; m1 = mn1;
        float rs0 = 0.f, rs1 = 0.f;
        #pragma unroll
        for (int nt = 0; nt < 8; nt++) {
            sAcc[nt][0] = exp2p(sAcc[nt][0] - m0); rs0 += sAcc[nt][0];
            sAcc[nt][1] = exp2p(sAcc[nt][1] - m0); rs0 += sAcc[nt][1];
            sAcc[nt][2] = exp2p(sAcc[nt][2] - m1); rs1 += sAcc[nt][2];
            sAcc[nt][3] = exp2p(sAcc[nt][3] - m1); rs1 += sAcc[nt][3];
        }
        rs0 += __shfl_xor_sync(0xffffffffu, rs0, 1);
        rs0 += __shfl_xor_sync(0xffffffffu, rs0, 2);
        rs1 += __shfl_xor_sync(0xffffffffu, rs1, 1);
        rs1 += __shfl_xor_sync(0xffffffffu, rs1, 2);
        l0 = l0 * sc0 + rs0;
        l1 = l1 * sc1 + rs1;
        #pragma unroll
        for (int dg = 0; dg < 8; dg++) {
            accO[dg][0] *= sc0; accO[dg][1] *= sc0;
            accO[dg][2] *= sc1; accO[dg][3] *= sc1;
        }

        // ---- P hi/lo fragments
        uint32_t phi[4][4], plo[4][4];
        #pragma unroll
        for (int j = 0; j < 4; j++) {
            hilo2(sAcc[2*j][0],   sAcc[2*j][1],   phi[j][0], plo[j][0]);
            hilo2(sAcc[2*j][2],   sAcc[2*j][3],   phi[j][1], plo[j][1]);
            hilo2(sAcc[2*j+1][0], sAcc[2*j+1][1], phi[j][2], plo[j][2]);
            hilo2(sAcc[2*j+1][2], sAcc[2*j+1][3], phi[j][3], plo[j][3]);
        }

        // ---- O += P V (3-term compensated)
        #pragma unroll
        for (int j = 0; j < 4; j++) {
            #pragma unroll
            for (int dgp = 0; dgp < 4; dgp++) {
                uint32_t vh[4], vl[4];
                int rr = j * 16 + ((lane >> 3) & 1) * 8 + (lane & 7);
                int cc = dgp * 2 + (lane >> 4);
                ldsm4t(vh, VHI + SWZ(rr, cc));
                ldsm4t(vl, VLO + SWZ(rr, cc));
                mma16816(accO[2*dgp],   phi[j], vh[0], vh[1]);
                mma16816(accO[2*dgp+1], phi[j], vh[2], vh[3]);
                mma16816(accO[2*dgp],   phi[j], vl[0], vl[1]);
                mma16816(accO[2*dgp+1], phi[j], vl[2], vl[3]);
                mma16816(accO[2*dgp],   plo[j], vh[0], vh[1]);
                mma16816(accO[2*dgp+1], plo[j], vh[2], vh[3]);
            }
        }
        __syncthreads();
    }

    float inv0 = 1.f / l0, inv1 = 1.f / l1;
    int row = b * NSEQ + qt * 128 + wid * 16 + (lane >> 2);
    __half* op0 = o + (size_t)row * INNER + h * DH + 2 * (lane & 3);
    __half* op1 = op0 + (size_t)8 * INNER;
    #pragma unroll
    for (int dg = 0; dg < 8; dg++) {
        *(__half2*)(op0 + dg * 8) = __floats2half2_rn(accO[dg][0] * inv0, accO[dg][1] * inv0);
        *(__half2*)(op1 + dg * 8) = __floats2half2_rn(accO[dg][2] * inv1, accO[dg][3] * inv1);
    }
}

// ---------------------------------------------------------------------------
extern "C" void kernel_launch(void* const* d_in, const int* in_sizes, int n_in,
                              void* d_out, int out_size)
{
    const float* x     = (const float*)d_in[0];
    const float* ln_g  = (const float*)d_in[1];
    const float* ln_b  = (const float*)d_in[2];
    const float* w_qkv = (const float*)d_in[3];
    const float* w_out = (const float*)d_in[4];
    const float* b_out = (const float*)d_in[5];
    float* out = (float*)d_out;

    __half *xn_h, *o_h, *wqkvT_h, *woutT_h;
    __half *q_hi, *q_lo, *k_hi, *k_lo, *v_hi, *v_lo;
    float *qkv, *cosT, *sinT;
    cudaGetSymbolAddress((void**)&xn_h,    g_xn_h);
    cudaGetSymbolAddress((void**)&qkv,     g_qkv);
    cudaGetSymbolAddress((void**)&o_h,     g_o_h);
    cudaGetSymbolAddress((void**)&wqkvT_h, g_wqkvT_h);
    cudaGetSymbolAddress((void**)&woutT_h, g_woutT_h);
    cudaGetSymbolAddress((void**)&cosT,    g_cosT);
    cudaGetSymbolAddress((void**)&sinT,    g_sinT);
    cudaGetSymbolAddress((void**)&q_hi,    g_q_hi);
    cudaGetSymbolAddress((void**)&q_lo,    g_q_lo);
    cudaGetSymbolAddress((void**)&k_hi,    g_k_hi);
    cudaGetSymbolAddress((void**)&k_lo,    g_k_lo);
    cudaGetSymbolAddress((void**)&v_hi,    g_v_hi);
    cudaGetSymbolAddress((void**)&v_lo,    g_v_lo);

    static int cfg_done = 0;
    if (!cfg_done) {
        cudaFuncSetAttribute(fa_kernel, cudaFuncAttributeMaxDynamicSharedMemorySize, 98304);
        cfg_done = 1;
    }

    ln_kernel<<<ROWS, 256>>>(x, ln_g, ln_b, xn_h);
    transpose_cvt_kernel<<<dim3(NQKV / 32, DIM / 32), 256>>>(w_qkv, wqkvT_h, DIM, NQKV);
    transpose_cvt_kernel<<<dim3(DIM / 32, INNER / 32), 256>>>(w_out, woutT_h, INNER, DIM);
    rope_table_kernel<<<(NSEQ * DH) / 256, 256>>>(cosT, sinT);

    hgemm<<<dim3(NQKV / 128, ROWS / 128), 256>>>(
        xn_h, wqkvT_h, nullptr, qkv, ROWS, NQKV, DIM, 0);

    rope_cvt_kernel<<<ROWS, 384>>>(qkv, cosT, sinT,
                                   q_hi, q_lo, k_hi, k_lo, v_hi, v_lo);

    fa_kernel<<<dim3(NSEQ / 128, HEADS, BATCH), 256, 98304>>>(
        q_hi, q_lo, k_hi, k_lo, v_hi, v_lo, o_h);

    hgemm<<<dim3(DIM / 128, ROWS / 128), 256>>>(
        o_h, woutT_h, b_out, out, ROWS, DIM, INNER, 1);
}

// round 6
// speedup vs baseline: 1.4057x; 1.4057x over previous
#include <cuda_runtime.h>
#include <cuda_fp16.h>
#include <math.h>
#include <stdint.h>

#define BATCH 4
#define NSEQ 2048
#define DIM 1024
#define HEADS 16
#define DH 64
#define INNER 1024
#define NQKV 3072
#define ROWS (BATCH*NSEQ)

// Scratch
__device__ __half g_xn_h[(size_t)ROWS * DIM];
__device__ float  g_qkv[(size_t)ROWS * NQKV];
__device__ __half g_o_h[(size_t)ROWS * INNER];
__device__ __half g_wqkvT_h[(size_t)NQKV * DIM];
__device__ __half g_woutT_h[(size_t)DIM * INNER];
__device__ float  g_cosT[(size_t)NSEQ * DH];
__device__ float  g_sinT[(size_t)NSEQ * DH];
// head-major tensors: [b, h, n, 64]; Q split hi/lo, K/V plain fp16
__device__ __half g_q_hi[(size_t)ROWS * INNER];
__device__ __half g_q_lo[(size_t)ROWS * INNER];
__device__ __half g_k_h[(size_t)ROWS * INNER];
__device__ __half g_v_h[(size_t)ROWS * INNER];

__device__ __forceinline__ uint32_t smem_u32(const void* p) {
    uint32_t a;
    asm("{ .reg .u64 t; cvta.to.shared.u64 t, %1; cvt.u32.u64 %0, t; }"
        : "=r"(a) : "l"(p));
    return a;
}
__device__ __forceinline__ void cp_async16(uint32_t dst, const void* src) {
    asm volatile("cp.async.cg.shared.global [%0], [%1], 16;"
                 :: "r"(dst), "l"(src) : "memory");
}
__device__ __forceinline__ void ldsm4(uint32_t* r, uint32_t addr) {
    asm volatile("ldmatrix.sync.aligned.m8n8.x4.shared.b16 {%0,%1,%2,%3}, [%4];"
                 : "=r"(r[0]), "=r"(r[1]), "=r"(r[2]), "=r"(r[3]) : "r"(addr));
}
__device__ __forceinline__ void ldsm4t(uint32_t* r, uint32_t addr) {
    asm volatile("ldmatrix.sync.aligned.m8n8.x4.trans.shared.b16 {%0,%1,%2,%3}, [%4];"
                 : "=r"(r[0]), "=r"(r[1]), "=r"(r[2]), "=r"(r[3]) : "r"(addr));
}
__device__ __forceinline__ void mma16816(float* c, const uint32_t* a, uint32_t b0, uint32_t b1) {
    asm volatile(
        "mma.sync.aligned.m16n8k16.row.col.f32.f16.f16.f32 "
        "{%0,%1,%2,%3}, {%4,%5,%6,%7}, {%8,%9}, {%0,%1,%2,%3};"
        : "+f"(c[0]), "+f"(c[1]), "+f"(c[2]), "+f"(c[3])
        : "r"(a[0]), "r"(a[1]), "r"(a[2]), "r"(a[3]), "r"(b0), "r"(b1));
}
__device__ __forceinline__ float exp2p(float x) {
    x = fmaxf(x, -126.f);
    float t = x + 12582912.f;
    float fi = t - 12582912.f;
    float f = x - fi;
    float p = 1.3333558146e-3f;
    p = fmaf(p, f, 9.6181291076e-3f);
    p = fmaf(p, f, 5.5504108665e-2f);
    p = fmaf(p, f, 2.4022650696e-1f);
    p = fmaf(p, f, 6.9314718056e-1f);
    p = fmaf(p, f, 1.0f);
    int ei = (int)fi;
    return __int_as_float(__float_as_int(p) + (ei << 23));
}
__device__ __forceinline__ uint32_t pack_h2(__half a, __half b) {
    __half2 t = __halves2half2(a, b);
    return *reinterpret_cast<uint32_t*>(&t);
}
__device__ __forceinline__ void hilo2(float a, float b, uint32_t& hi, uint32_t& lo) {
    __half ha = __float2half_rn(a), hb = __float2half_rn(b);
    hi = pack_h2(ha, hb);
    lo = pack_h2(__float2half_rn(a - __half2float(ha)),
                 __float2half_rn(b - __half2float(hb)));
}
#define SWZ(r, g) ((uint32_t)((r) * 128 + (((g) ^ ((r) & 7)) * 16)))

// ---------------------------------------------------------------------------
// LayerNorm -> half
// ---------------------------------------------------------------------------
__global__ __launch_bounds__(256) void ln_kernel(
    const float* __restrict__ x, const float* __restrict__ gg,
    const float* __restrict__ bb, __half* __restrict__ out)
{
    int row = blockIdx.x;
    int tid = threadIdx.x;
    const float4* xr = (const float4*)(x + (size_t)row * DIM);
    float4 v = xr[tid];
    float s  = v.x + v.y + v.z + v.w;
    float s2 = fmaf(v.x, v.x, fmaf(v.y, v.y, fmaf(v.z, v.z, v.w * v.w)));
    #pragma unroll
    for (int o = 16; o; o >>= 1) {
        s  += __shfl_xor_sync(0xffffffffu, s, o);
        s2 += __shfl_xor_sync(0xffffffffu, s2, o);
    }
    __shared__ float rs[8], rs2[8];
    __shared__ float mu_s, rstd_s;
    int w = tid >> 5;
    if ((tid & 31) == 0) { rs[w] = s; rs2[w] = s2; }
    __syncthreads();
    if (tid == 0) {
        float a = 0.f, a2 = 0.f;
        #pragma unroll
        for (int i = 0; i < 8; i++) { a += rs[i]; a2 += rs2[i]; }
        float mu = a * (1.f / DIM);
        float var = a2 * (1.f / DIM) - mu * mu;
        mu_s = mu;
        rstd_s = rsqrtf(var + 1e-5f);
    }
    __syncthreads();
    float mu = mu_s, r = rstd_s;
    float4 g4 = ((const float4*)gg)[tid];
    float4 b4 = ((const float4*)bb)[tid];
    __half2* orow = (__half2*)(out + (size_t)row * DIM);
    orow[tid * 2]     = __floats2half2_rn((v.x - mu) * r * g4.x + b4.x,
                                          (v.y - mu) * r * g4.y + b4.y);
    orow[tid * 2 + 1] = __floats2half2_rn((v.z - mu) * r * g4.z + b4.z,
                                          (v.w - mu) * r * g4.w + b4.w);
}

__global__ __launch_bounds__(256) void transpose_cvt_kernel(
    const float* __restrict__ src, __half* __restrict__ dst, int K, int N)
{
    __shared__ float t[32][33];
    int n0 = blockIdx.x * 32, k0 = blockIdx.y * 32;
    int tx = threadIdx.x & 31, ty = threadIdx.x >> 5;
    #pragma unroll
    for (int i = 0; i < 4; i++)
        t[ty + 8 * i][tx] = src[(size_t)(k0 + ty + 8 * i) * N + n0 + tx];
    __syncthreads();
    #pragma unroll
    for (int i = 0; i < 4; i++)
        dst[(size_t)(n0 + ty + 8 * i) * K + k0 + tx] = __float2half(t[tx][ty + 8 * i]);
}

// ---------------------------------------------------------------------------
// HGEMM (unchanged)
// ---------------------------------------------------------------------------
__global__ __launch_bounds__(256) void hgemm(
    const __half* __restrict__ A, const __half* __restrict__ BT,
    const float* __restrict__ bias, float* __restrict__ C,
    int M, int N, int K, int has_bias)
{
    __shared__ __align__(128) char sm[32768];
    uint32_t sbase = smem_u32(sm);
    int tid = threadIdx.x, lane = tid & 31, wid = tid >> 5;
    int wm = (wid >> 2) * 64, wn = (wid & 3) * 32;
    int row0 = blockIdx.y * 128, col0 = blockIdx.x * 128;
    const __half* Ag = A  + (size_t)row0 * K;
    const __half* Bg = BT + (size_t)col0 * K;

    float acc[4][4][4];
    #pragma unroll
    for (int i = 0; i < 4; i++)
        #pragma unroll
        for (int j = 0; j < 4; j++)
            #pragma unroll
            for (int q = 0; q < 4; q++) acc[i][j][q] = 0.f;

    #define SWA(base, r, c) ((base) + (uint32_t)((r) * 64 + (((c) ^ (((r) >> 1) & 3)) * 16)))
    #define LOAD_STAGE(stage, k0)                                              \
    {                                                                          \
        uint32_t abase = sbase + (stage) * 8192;                               \
        uint32_t bbase = sbase + 16384 + (stage) * 8192;                       \
        _Pragma("unroll")                                                      \
        for (int t = 0; t < 2; t++) {                                          \
            int idx = tid + t * 256;                                           \
            int r = idx >> 2, c = idx & 3;                                     \
            cp_async16(SWA(abase, r, c), Ag + (size_t)r * K + (k0) + c * 8);   \
            cp_async16(SWA(bbase, r, c), Bg + (size_t)r * K + (k0) + c * 8);   \
        }                                                                      \
        asm volatile("cp.async.commit_group;" ::: "memory");                   \
    }

    LOAD_STAGE(0, 0);
    const int NK = K >> 5;
    for (int kt = 0; kt < NK; kt++) {
        int cur = kt & 1;
        if (kt + 1 < NK) {
            LOAD_STAGE(1 - cur, (kt + 1) << 5);
            asm volatile("cp.async.wait_group 1;" ::: "memory");
        } else {
            asm volatile("cp.async.wait_group 0;" ::: "memory");
        }
        __syncthreads();
        uint32_t abase = sbase + cur * 8192;
        uint32_t bbase = sbase + 16384 + cur * 8192;
        #pragma unroll
        for (int ks = 0; ks < 2; ks++) {
            uint32_t a[4][4], b[2][4];
            #pragma unroll
            for (int mf = 0; mf < 4; mf++) {
                int rr = wm + mf * 16 + ((lane >> 3) & 1) * 8 + (lane & 7);
                int cc = ks * 2 + (lane >> 4);
                ldsm4(a[mf], SWA(abase, rr, cc));
            }
            #pragma unroll
            for (int n2 = 0; n2 < 2; n2++) {
                int rr = wn + n2 * 16 + ((lane >> 4) & 1) * 8 + (lane & 7);
                int cc = ks * 2 + ((lane >> 3) & 1);
                ldsm4(b[n2], SWA(bbase, rr, cc));
            }
            #pragma unroll
            for (int mf = 0; mf < 4; mf++)
                #pragma unroll
                for (int nf = 0; nf < 4; nf++)
                    mma16816(acc[mf][nf], a[mf],
                             b[nf >> 1][(nf & 1) * 2], b[nf >> 1][(nf & 1) * 2 + 1]);
        }
        __syncthreads();
    }
    #pragma unroll
    for (int mf = 0; mf < 4; mf++) {
        int grow = row0 + wm + mf * 16 + (lane >> 2);
        #pragma unroll
        for (int nf = 0; nf < 4; nf++) {
            int gcol = col0 + wn + nf * 8 + (lane & 3) * 2;
            float bx = 0.f, by = 0.f;
            if (has_bias) {
                float2 bb = *(const float2*)(bias + gcol);
                bx = bb.x; by = bb.y;
            }
            *(float2*)(C + (size_t)grow * N + gcol) =
                make_float2(acc[mf][nf][0] + bx, acc[mf][nf][1] + by);
            *(float2*)(C + (size_t)(grow + 8) * N + gcol) =
                make_float2(acc[mf][nf][2] + bx, acc[mf][nf][3] + by);
        }
    }
}

// ---------------------------------------------------------------------------
// RoPE tables
// ---------------------------------------------------------------------------
__global__ __launch_bounds__(256) void rope_table_kernel(
    float* __restrict__ cosT, float* __restrict__ sinT)
{
    int idx = blockIdx.x * blockDim.x + threadIdx.x;
    int pos = idx >> 6, d = idx & 63;
    float fr = powf(10000.f, -(float)(d >> 1) * (1.f / 32.f));
    float a = (float)pos * fr;
    float s, c;
    sincosf(a, &s, &c);
    cosT[idx] = c;
    sinT[idx] = s;
}

// ---------------------------------------------------------------------------
// Fused RoPE + convert + [b,h,n,64] relayout.
// Q -> hi/lo fp16 (scaled); K,V -> plain fp16.
// ---------------------------------------------------------------------------
__global__ __launch_bounds__(384) void rope_cvt_kernel(
    const float* __restrict__ qkv,
    const float* __restrict__ cosT, const float* __restrict__ sinT,
    __half* __restrict__ q_hi, __half* __restrict__ q_lo,
    __half* __restrict__ k_h, __half* __restrict__ v_h)
{
    const float QSC = 0.125f * 1.44269504089f;
    int tid = threadIdx.x;
    int part = tid >> 7;            // 0=q 1=k 2=v
    int sub = tid & 127;
    int h = sub >> 3, g = sub & 7, d0 = g * 8;
    int row = blockIdx.x;
    int b = row >> 11, pos = row & (NSEQ - 1);

    const float* src = qkv + (size_t)row * NQKV + part * INNER + h * DH;
    float f[8];
    *(float4*)&f[0] = *(const float4*)(src + d0);
    *(float4*)&f[4] = *(const float4*)(src + d0 + 4);

    if (part < 2) {
        int d0p = d0 ^ 32;
        float pr[8];
        *(float4*)&pr[0] = *(const float4*)(src + d0p);
        *(float4*)&pr[4] = *(const float4*)(src + d0p + 4);
        float sgn = (d0 < 32) ? -1.f : 1.f;
        #pragma unroll
        for (int j = 0; j < 8; j++) {
            float c = cosT[pos * DH + d0 + j];
            float s = sinT[pos * DH + d0 + j];
            f[j] = f[j] * c + sgn * pr[j] * s;
        }
    }

    size_t off = ((size_t)(b * HEADS + h) * NSEQ + pos) * DH + d0;
    if (part == 0) {
        uint32_t ph[4], pl[4];
        #pragma unroll
        for (int i = 0; i < 4; i++) hilo2(f[2*i] * QSC, f[2*i+1] * QSC, ph[i], pl[i]);
        *(uint4*)(q_hi + off) = make_uint4(ph[0], ph[1], ph[2], ph[3]);
        *(uint4*)(q_lo + off) = make_uint4(pl[0], pl[1], pl[2], pl[3]);
    } else {
        uint32_t p[4];
        #pragma unroll
        for (int i = 0; i < 4; i++) {
            __half2 t = __floats2half2_rn(f[2*i], f[2*i+1]);
            p[i] = *reinterpret_cast<uint32_t*>(&t);
        }
        __half* dst = (part == 1) ? k_h : v_h;
        *(uint4*)(dst + off) = make_uint4(p[0], p[1], p[2], p[3]);
    }
}

// ---------------------------------------------------------------------------
// Flash attention v3: Q hi/lo x K plain, P hi/lo x V plain (2-term).
// Block: 128 q-rows x head x batch, 8 warps, 64-key tiles.
// smem: Q 32KB + 2 stages x 16KB = 64KB dynamic.
// ---------------------------------------------------------------------------
__global__ __launch_bounds__(256) void fa_kernel(
    const __half* __restrict__ q_hi, const __half* __restrict__ q_lo,
    const __half* __restrict__ k_h, const __half* __restrict__ v_h,
    __half* __restrict__ o)
{
    extern __shared__ __align__(128) char sm[];
    uint32_t sb = smem_u32(sm);
    const uint32_t QHI = 0, QLO = 16384, STG = 32768;
    // stage layout: K at +0 (8KB), V at +8192 (8KB); stage size 16384

    int tid = threadIdx.x, lane = tid & 31, wid = tid >> 5;
    int qt = blockIdx.x, h = blockIdx.y, b = blockIdx.z;
    size_t hb = (size_t)(b * HEADS + h) * NSEQ;

    // ---- Q via cp.async: hi/lo, 128 rows each
    {
        int arr = tid >> 7, r = tid & 127;
        const __half* src = (arr ? q_lo : q_hi) + (hb + qt * 128 + r) * DH;
        uint32_t dst = sb + (arr ? QLO : QHI);
        #pragma unroll
        for (int g = 0; g < 8; g++)
            cp_async16(dst + SWZ(r, g), src + g * 8);
        asm volatile("cp.async.commit_group;" ::: "memory");
    }
    // ---- KV loader: 2 arrays x 64 rows x 2 half-rows
    int kvarr = tid >> 7, kvr = (tid >> 1) & 63, kvhalf = tid & 1;
    const __half* kvbase = (kvarr ? v_h : k_h) + hb * DH;
    #define LOAD_KV(buf, s0)                                                   \
    {                                                                          \
        uint32_t dst = sb + STG + (buf) * 16384 + kvarr * 8192;                \
        const __half* srcp = kvbase + ((size_t)(s0) + kvr) * DH + kvhalf * 32; \
        _Pragma("unroll")                                                      \
        for (int g = 0; g < 4; g++)                                            \
            cp_async16(dst + SWZ(kvr, kvhalf * 4 + g), srcp + g * 8);          \
        asm volatile("cp.async.commit_group;" ::: "memory");                   \
    }

    LOAD_KV(0, 0);
    asm volatile("cp.async.wait_group 1;" ::: "memory");  // Q arrived
    __syncthreads();

    uint32_t qhi[4][4], qlo[4][4];
    #pragma unroll
    for (int kt = 0; kt < 4; kt++) {
        int rr = wid * 16 + ((lane >> 3) & 1) * 8 + (lane & 7);
        int gg = 2 * kt + (lane >> 4);
        ldsm4(qhi[kt], sb + QHI + SWZ(rr, gg));
        ldsm4(qlo[kt], sb + QLO + SWZ(rr, gg));
    }

    float accO[8][4];
    #pragma unroll
    for (int i = 0; i < 8; i++)
        #pragma unroll
        for (int j = 0; j < 4; j++) accO[i][j] = 0.f;
    float m0 = -1e30f, m1 = -1e30f, l0 = 0.f, l1 = 0.f;

    const int NT = NSEQ / 64;
    for (int kt = 0; kt < NT; kt++) {
        int cur = kt & 1;
        if (kt + 1 < NT) {
            LOAD_KV(1 - cur, (kt + 1) * 64);
            asm volatile("cp.async.wait_group 1;" ::: "memory");
        } else {
            asm volatile("cp.async.wait_group 0;" ::: "memory");
        }
        __syncthreads();
        uint32_t KS = sb + STG + cur * 16384;
        uint32_t VS = KS + 8192;

        // ---- S = (q_hi + q_lo) K^T  (2 MMAs per acc fragment)
        float sAcc[8][4];
        #pragma unroll
        for (int i = 0; i < 8; i++)
            #pragma unroll
            for (int j = 0; j < 4; j++) sAcc[i][j] = 0.f;
        #pragma unroll
        for (int kk = 0; kk < 4; kk++) {
            #pragma unroll
            for (int g = 0; g < 4; g++) {
                uint32_t bh[4];
                int rr = g * 16 + ((lane >> 4) & 1) * 8 + (lane & 7);
                int cc = kk * 2 + ((lane >> 3) & 1);
                ldsm4(bh, KS + SWZ(rr, cc));
                mma16816(sAcc[2*g],   qhi[kk], bh[0], bh[1]);
                mma16816(sAcc[2*g+1], qhi[kk], bh[2], bh[3]);
                mma16816(sAcc[2*g],   qlo[kk], bh[0], bh[1]);
                mma16816(sAcc[2*g+1], qlo[kk], bh[2], bh[3]);
            }
        }

        // ---- online softmax
        float mx0 = -1e30f, mx1 = -1e30f;
        #pragma unroll
        for (int nt = 0; nt < 8; nt++) {
            mx0 = fmaxf(mx0, fmaxf(sAcc[nt][0], sAcc[nt][1]));
            mx1 = fmaxf(mx1, fmaxf(sAcc[nt][2], sAcc[nt][3]));
        }
        mx0 = fmaxf(mx0, __shfl_xor_sync(0xffffffffu, mx0, 1));
        mx0 = fmaxf(mx0, __shfl_xor_sync(0xffffffffu, mx0, 2));
        mx1 = fmaxf(mx1, __shfl_xor_sync(0xffffffffu, mx1, 1));
        mx1 = fmaxf(mx1, __shfl_xor_sync(0xffffffffu, mx1, 2));
        float mn0 = fmaxf(m0, mx0), mn1 = fmaxf(m1, mx1);
        float sc0 = exp2p(m0 - mn0), sc1 = exp2p(m1 - mn1);
        m0 = mn0; m1 = mn1;
        float rs0 = 0.f, rs1 = 0.f;
        #pragma unroll
        for (int nt = 0; nt < 8; nt++) {
            sAcc[nt][0] = exp2p(sAcc[nt][0] - m0); rs0 += sAcc[nt][0];
            sAcc[nt][1] = exp2p(sAcc[nt][1] - m0); rs0 += sAcc[nt][1];
            sAcc[nt][2] = exp2p(sAcc[nt][2] - m1); rs1 += sAcc[nt][2];
            sAcc[nt][3] = exp2p(sAcc[nt][3] - m1); rs1 += sAcc[nt][3];
        }
        rs0 += __shfl_xor_sync(0xffffffffu, rs0, 1);
        rs0 += __shfl_xor_sync(0xffffffffu, rs0, 2);
        rs1 += __shfl_xor_sync(0xffffffffu, rs1, 1);
        rs1 += __shfl_xor_sync(0xffffffffu, rs1, 2);
        l0 = l0 * sc0 + rs0;
        l1 = l1 * sc1 + rs1;
        #pragma unroll
        for (int dg = 0; dg < 8; dg++) {
            accO[dg][0] *= sc0; accO[dg][1] *= sc0;
            accO[dg][2] *= sc1; accO[dg][3] *= sc1;
        }

        // ---- P hi/lo fragments
        uint32_t phi[4][4], plo[4][4];
        #pragma unroll
        for (int j = 0; j < 4; j++) {
            hilo2(sAcc[2*j][0],   sAcc[2*j][1],   phi[j][0], plo[j][0]);
            hilo2(sAcc[2*j][2],   sAcc[2*j][3],   phi[j][1], plo[j][1]);
            hilo2(sAcc[2*j+1][0], sAcc[2*j+1][1], phi[j][2], plo[j][2]);
            hilo2(sAcc[2*j+1][2], sAcc[2*j+1][3], phi[j][3], plo[j][3]);
        }

        // ---- O += (P_hi + P_lo) V
        #pragma unroll
        for (int j = 0; j < 4; j++) {
            #pragma unroll
            for (int dgp = 0; dgp < 4; dgp++) {
                uint32_t vh[4];
                int rr = j * 16 + ((lane >> 3) & 1) * 8 + (lane & 7);
                int cc = dgp * 2 + (lane >> 4);
                ldsm4t(vh, VS + SWZ(rr, cc));
                mma16816(accO[2*dgp],   phi[j], vh[0], vh[1]);
                mma16816(accO[2*dgp+1], phi[j], vh[2], vh[3]);
                mma16816(accO[2*dgp],   plo[j], vh[0], vh[1]);
                mma16816(accO[2*dgp+1], plo[j], vh[2], vh[3]);
            }
        }
        __syncthreads();
    }

    float inv0 = 1.f / l0, inv1 = 1.f / l1;
    int row = b * NSEQ + qt * 128 + wid * 16 + (lane >> 2);
    __half* op0 = o + (size_t)row * INNER + h * DH + 2 * (lane & 3);
    __half* op1 = op0 + (size_t)8 * INNER;
    #pragma unroll
    for (int dg = 0; dg < 8; dg++) {
        *(__half2*)(op0 + dg * 8) = __floats2half2_rn(accO[dg][0] * inv0, accO[dg][1] * inv0);
        *(__half2*)(op1 + dg * 8) = __floats2half2_rn(accO[dg][2] * inv1, accO[dg][3] * inv1);
    }
}

// ---------------------------------------------------------------------------
extern "C" void kernel_launch(void* const* d_in, const int* in_sizes, int n_in,
                              void* d_out, int out_size)
{
    const float* x     = (const float*)d_in[0];
    const float* ln_g  = (const float*)d_in[1];
    const float* ln_b  = (const float*)d_in[2];
    const float* w_qkv = (const float*)d_in[3];
    const float* w_out = (const float*)d_in[4];
    const float* b_out = (const float*)d_in[5];
    float* out = (float*)d_out;

    __half *xn_h, *o_h, *wqkvT_h, *woutT_h;
    __half *q_hi, *q_lo, *k_h, *v_h;
    float *qkv, *cosT, *sinT;
    cudaGetSymbolAddress((void**)&xn_h,    g_xn_h);
    cudaGetSymbolAddress((void**)&qkv,     g_qkv);
    cudaGetSymbolAddress((void**)&o_h,     g_o_h);
    cudaGetSymbolAddress((void**)&wqkvT_h, g_wqkvT_h);
    cudaGetSymbolAddress((void**)&woutT_h, g_woutT_h);
    cudaGetSymbolAddress((void**)&cosT,    g_cosT);
    cudaGetSymbolAddress((void**)&sinT,    g_sinT);
    cudaGetSymbolAddress((void**)&q_hi,    g_q_hi);
    cudaGetSymbolAddress((void**)&q_lo,    g_q_lo);
    cudaGetSymbolAddress((void**)&k_h,     g_k_h);
    cudaGetSymbolAddress((void**)&v_h,     g_v_h);

    static int cfg_done = 0;
    if (!cfg_done) {
        cudaFuncSetAttribute(fa_kernel, cudaFuncAttributeMaxDynamicSharedMemorySize, 65536);
        cfg_done = 1;
    }

    ln_kernel<<<ROWS, 256>>>(x, ln_g, ln_b, xn_h);
    transpose_cvt_kernel<<<dim3(NQKV / 32, DIM / 32), 256>>>(w_qkv, wqkvT_h, DIM, NQKV);
    transpose_cvt_kernel<<<dim3(DIM / 32, INNER / 32), 256>>>(w_out, woutT_h, INNER, DIM);
    rope_table_kernel<<<(NSEQ * DH) / 256, 256>>>(cosT, sinT);

    hgemm<<<dim3(NQKV / 128, ROWS / 128), 256>>>(
        xn_h, wqkvT_h, nullptr, qkv, ROWS, NQKV, DIM, 0);

    rope_cvt_kernel<<<ROWS, 384>>>(qkv, cosT, sinT, q_hi, q_lo, k_h, v_h);

    fa_kernel<<<dim3(NSEQ / 128, HEADS, BATCH), 256, 65536>>>(
        q_hi, q_lo, k_h, v_h, o_h);

    hgemm<<<dim3(DIM / 128, ROWS / 128), 256>>>(
        o_h, woutT_h, b_out, out, ROWS, DIM, INNER, 1);
}

// round 7
// speedup vs baseline: 1.5816x; 1.1251x over previous
#include <cuda_runtime.h>
#include <cuda_fp16.h>
#include <math.h>
#include <stdint.h>

#define BATCH 4
#define NSEQ 2048
#define DIM 1024
#define HEADS 16
#define DH 64
#define INNER 1024
#define NQKV 3072
#define ROWS (BATCH*NSEQ)

// Scratch
__device__ __half g_xn_h[(size_t)ROWS * DIM];
__device__ float  g_qkv[(size_t)ROWS * NQKV];
__device__ __half g_o_h[(size_t)ROWS * INNER];
__device__ __half g_wqkvT_h[(size_t)NQKV * DIM];
__device__ __half g_woutT_h[(size_t)DIM * INNER];
__device__ float  g_cosT[(size_t)NSEQ * DH];
__device__ float  g_sinT[(size_t)NSEQ * DH];
// head-major tensors: [b, h, n, 64]; Q split hi/lo, K/V plain fp16
__device__ __half g_q_hi[(size_t)ROWS * INNER];
__device__ __half g_q_lo[(size_t)ROWS * INNER];
__device__ __half g_k_h[(size_t)ROWS * INNER];
__device__ __half g_v_h[(size_t)ROWS * INNER];

__device__ __forceinline__ uint32_t smem_u32(const void* p) {
    uint32_t a;
    asm("{ .reg .u64 t; cvta.to.shared.u64 t, %1; cvt.u32.u64 %0, t; }"
        : "=r"(a) : "l"(p));
    return a;
}
__device__ __forceinline__ void cp_async16(uint32_t dst, const void* src) {
    asm volatile("cp.async.cg.shared.global [%0], [%1], 16;"
                 :: "r"(dst), "l"(src) : "memory");
}
__device__ __forceinline__ void ldsm4(uint32_t* r, uint32_t addr) {
    asm volatile("ldmatrix.sync.aligned.m8n8.x4.shared.b16 {%0,%1,%2,%3}, [%4];"
                 : "=r"(r[0]), "=r"(r[1]), "=r"(r[2]), "=r"(r[3]) : "r"(addr));
}
__device__ __forceinline__ void ldsm4t(uint32_t* r, uint32_t addr) {
    asm volatile("ldmatrix.sync.aligned.m8n8.x4.trans.shared.b16 {%0,%1,%2,%3}, [%4];"
                 : "=r"(r[0]), "=r"(r[1]), "=r"(r[2]), "=r"(r[3]) : "r"(addr));
}
__device__ __forceinline__ void mma16816(float* c, const uint32_t* a, uint32_t b0, uint32_t b1) {
    asm volatile(
        "mma.sync.aligned.m16n8k16.row.col.f32.f16.f16.f32 "
        "{%0,%1,%2,%3}, {%4,%5,%6,%7}, {%8,%9}, {%0,%1,%2,%3};"
        : "+f"(c[0]), "+f"(c[1]), "+f"(c[2]), "+f"(c[3])
        : "r"(a[0]), "r"(a[1]), "r"(a[2]), "r"(a[3]), "r"(b0), "r"(b1));
}
__device__ __forceinline__ float exp2p(float x) {
    x = fmaxf(x, -126.f);
    float t = x + 12582912.f;
    float fi = t - 12582912.f;
    float f = x - fi;
    float p = 1.3333558146e-3f;
    p = fmaf(p, f, 9.6181291076e-3f);
    p = fmaf(p, f, 5.5504108665e-2f);
    p = fmaf(p, f, 2.4022650696e-1f);
    p = fmaf(p, f, 6.9314718056e-1f);
    p = fmaf(p, f, 1.0f);
    int ei = (int)fi;
    return __int_as_float(__float_as_int(p) + (ei << 23));
}
__device__ __forceinline__ uint32_t pack_h2(__half a, __half b) {
    __half2 t = __halves2half2(a, b);
    return *reinterpret_cast<uint32_t*>(&t);
}
__device__ __forceinline__ void hilo2(float a, float b, uint32_t& hi, uint32_t& lo) {
    __half ha = __float2half_rn(a), hb = __float2half_rn(b);
    hi = pack_h2(ha, hb);
    lo = pack_h2(__float2half_rn(a - __half2float(ha)),
                 __float2half_rn(b - __half2float(hb)));
}
#define SWZ(r, g) ((uint32_t)((r) * 128 + (((g) ^ ((r) & 7)) * 16)))

// ---------------------------------------------------------------------------
// LayerNorm -> half
// ---------------------------------------------------------------------------
__global__ __launch_bounds__(256) void ln_kernel(
    const float* __restrict__ x, const float* __restrict__ gg,
    const float* __restrict__ bb, __half* __restrict__ out)
{
    int row = blockIdx.x;
    int tid = threadIdx.x;
    const float4* xr = (const float4*)(x + (size_t)row * DIM);
    float4 v = xr[tid];
    float s  = v.x + v.y + v.z + v.w;
    float s2 = fmaf(v.x, v.x, fmaf(v.y, v.y, fmaf(v.z, v.z, v.w * v.w)));
    #pragma unroll
    for (int o = 16; o; o >>= 1) {
        s  += __shfl_xor_sync(0xffffffffu, s, o);
        s2 += __shfl_xor_sync(0xffffffffu, s2, o);
    }
    __shared__ float rs[8], rs2[8];
    __shared__ float mu_s, rstd_s;
    int w = tid >> 5;
    if ((tid & 31) == 0) { rs[w] = s; rs2[w] = s2; }
    __syncthreads();
    if (tid == 0) {
        float a = 0.f, a2 = 0.f;
        #pragma unroll
        for (int i = 0; i < 8; i++) { a += rs[i]; a2 += rs2[i]; }
        float mu = a * (1.f / DIM);
        float var = a2 * (1.f / DIM) - mu * mu;
        mu_s = mu;
        rstd_s = rsqrtf(var + 1e-5f);
    }
    __syncthreads();
    float mu = mu_s, r = rstd_s;
    float4 g4 = ((const float4*)gg)[tid];
    float4 b4 = ((const float4*)bb)[tid];
    __half2* orow = (__half2*)(out + (size_t)row * DIM);
    orow[tid * 2]     = __floats2half2_rn((v.x - mu) * r * g4.x + b4.x,
                                          (v.y - mu) * r * g4.y + b4.y);
    orow[tid * 2 + 1] = __floats2half2_rn((v.z - mu) * r * g4.z + b4.z,
                                          (v.w - mu) * r * g4.w + b4.w);
}

__global__ __launch_bounds__(256) void transpose_cvt_kernel(
    const float* __restrict__ src, __half* __restrict__ dst, int K, int N)
{
    __shared__ float t[32][33];
    int n0 = blockIdx.x * 32, k0 = blockIdx.y * 32;
    int tx = threadIdx.x & 31, ty = threadIdx.x >> 5;
    #pragma unroll
    for (int i = 0; i < 4; i++)
        t[ty + 8 * i][tx] = src[(size_t)(k0 + ty + 8 * i) * N + n0 + tx];
    __syncthreads();
    #pragma unroll
    for (int i = 0; i < 4; i++)
        dst[(size_t)(n0 + ty + 8 * i) * K + k0 + tx] = __float2half(t[tx][ty + 8 * i]);
}

// ---------------------------------------------------------------------------
// HGEMM: 3-stage cp.async pipeline. C fp32 = A(h) @ BT(h)^T (+bias)
// ---------------------------------------------------------------------------
__global__ __launch_bounds__(256) void hgemm(
    const __half* __restrict__ A, const __half* __restrict__ BT,
    const float* __restrict__ bias, float* __restrict__ C,
    int M, int N, int K, int has_bias)
{
    __shared__ __align__(128) char sm[49152];  // A: 3x8KB at 0, B: 3x8KB at 24576
    uint32_t sbase = smem_u32(sm);
    int tid = threadIdx.x, lane = tid & 31, wid = tid >> 5;
    int wm = (wid >> 2) * 64, wn = (wid & 3) * 32;
    int row0 = blockIdx.y * 128, col0 = blockIdx.x * 128;
    const __half* Ag = A  + (size_t)row0 * K;
    const __half* Bg = BT + (size_t)col0 * K;

    float acc[4][4][4];
    #pragma unroll
    for (int i = 0; i < 4; i++)
        #pragma unroll
        for (int j = 0; j < 4; j++)
            #pragma unroll
            for (int q = 0; q < 4; q++) acc[i][j][q] = 0.f;

    #define SWA(base, r, c) ((base) + (uint32_t)((r) * 64 + (((c) ^ (((r) >> 1) & 3)) * 16)))
    #define LOAD_STAGE(stage, k0)                                              \
    {                                                                          \
        uint32_t abase = sbase + (stage) * 8192;                               \
        uint32_t bbase = sbase + 24576 + (stage) * 8192;                       \
        _Pragma("unroll")                                                      \
        for (int t = 0; t < 2; t++) {                                          \
            int idx = tid + t * 256;                                           \
            int r = idx >> 2, c = idx & 3;                                     \
            cp_async16(SWA(abase, r, c), Ag + (size_t)r * K + (k0) + c * 8);   \
            cp_async16(SWA(bbase, r, c), Bg + (size_t)r * K + (k0) + c * 8);   \
        }                                                                      \
        asm volatile("cp.async.commit_group;" ::: "memory");                   \
    }

    const int NK = K >> 5;
    LOAD_STAGE(0, 0);
    if (NK > 1) LOAD_STAGE(1, 32);

    for (int kt = 0; kt < NK; kt++) {
        int cur = kt % 3;
        if (kt + 2 < NK) {
            LOAD_STAGE((kt + 2) % 3, (kt + 2) << 5);
            asm volatile("cp.async.wait_group 2;" ::: "memory");
        } else if (kt + 1 < NK) {
            asm volatile("cp.async.wait_group 1;" ::: "memory");
        } else {
            asm volatile("cp.async.wait_group 0;" ::: "memory");
        }
        __syncthreads();
        uint32_t abase = sbase + cur * 8192;
        uint32_t bbase = sbase + 24576 + cur * 8192;
        #pragma unroll
        for (int ks = 0; ks < 2; ks++) {
            uint32_t a[4][4], b[2][4];
            #pragma unroll
            for (int mf = 0; mf < 4; mf++) {
                int rr = wm + mf * 16 + ((lane >> 3) & 1) * 8 + (lane & 7);
                int cc = ks * 2 + (lane >> 4);
                ldsm4(a[mf], SWA(abase, rr, cc));
            }
            #pragma unroll
            for (int n2 = 0; n2 < 2; n2++) {
                int rr = wn + n2 * 16 + ((lane >> 4) & 1) * 8 + (lane & 7);
                int cc = ks * 2 + ((lane >> 3) & 1);
                ldsm4(b[n2], SWA(bbase, rr, cc));
            }
            #pragma unroll
            for (int mf = 0; mf < 4; mf++)
                #pragma unroll
                for (int nf = 0; nf < 4; nf++)
                    mma16816(acc[mf][nf], a[mf],
                             b[nf >> 1][(nf & 1) * 2], b[nf >> 1][(nf & 1) * 2 + 1]);
        }
        __syncthreads();
    }
    #pragma unroll
    for (int mf = 0; mf < 4; mf++) {
        int grow = row0 + wm + mf * 16 + (lane >> 2);
        #pragma unroll
        for (int nf = 0; nf < 4; nf++) {
            int gcol = col0 + wn + nf * 8 + (lane & 3) * 2;
            float bx = 0.f, by = 0.f;
            if (has_bias) {
                float2 bb = *(const float2*)(bias + gcol);
                bx = bb.x; by = bb.y;
            }
            *(float2*)(C + (size_t)grow * N + gcol) =
                make_float2(acc[mf][nf][0] + bx, acc[mf][nf][1] + by);
            *(float2*)(C + (size_t)(grow + 8) * N + gcol) =
                make_float2(acc[mf][nf][2] + bx, acc[mf][nf][3] + by);
        }
    }
}

// ---------------------------------------------------------------------------
// RoPE tables
// ---------------------------------------------------------------------------
__global__ __launch_bounds__(256) void rope_table_kernel(
    float* __restrict__ cosT, float* __restrict__ sinT)
{
    int idx = blockIdx.x * blockDim.x + threadIdx.x;
    int pos = idx >> 6, d = idx & 63;
    float fr = powf(10000.f, -(float)(d >> 1) * (1.f / 32.f));
    float a = (float)pos * fr;
    float s, c;
    sincosf(a, &s, &c);
    cosT[idx] = c;
    sinT[idx] = s;
}

// ---------------------------------------------------------------------------
// Fused RoPE + convert + [b,h,n,64] relayout.
// ---------------------------------------------------------------------------
__global__ __launch_bounds__(384) void rope_cvt_kernel(
    const float* __restrict__ qkv,
    const float* __restrict__ cosT, const float* __restrict__ sinT,
    __half* __restrict__ q_hi, __half* __restrict__ q_lo,
    __half* __restrict__ k_h, __half* __restrict__ v_h)
{
    const float QSC = 0.125f * 1.44269504089f;
    int tid = threadIdx.x;
    int part = tid >> 7;
    int sub = tid & 127;
    int h = sub >> 3, g = sub & 7, d0 = g * 8;
    int row = blockIdx.x;
    int b = row >> 11, pos = row & (NSEQ - 1);

    const float* src = qkv + (size_t)row * NQKV + part * INNER + h * DH;
    float f[8];
    *(float4*)&f[0] = *(const float4*)(src + d0);
    *(float4*)&f[4] = *(const float4*)(src + d0 + 4);

    if (part < 2) {
        int d0p = d0 ^ 32;
        float pr[8];
        *(float4*)&pr[0] = *(const float4*)(src + d0p);
        *(float4*)&pr[4] = *(const float4*)(src + d0p + 4);
        float sgn = (d0 < 32) ? -1.f : 1.f;
        #pragma unroll
        for (int j = 0; j < 8; j++) {
            float c = cosT[pos * DH + d0 + j];
            float s = sinT[pos * DH + d0 + j];
            f[j] = f[j] * c + sgn * pr[j] * s;
        }
    }

    size_t off = ((size_t)(b * HEADS + h) * NSEQ + pos) * DH + d0;
    if (part == 0) {
        uint32_t ph[4], pl[4];
        #pragma unroll
        for (int i = 0; i < 4; i++) hilo2(f[2*i] * QSC, f[2*i+1] * QSC, ph[i], pl[i]);
        *(uint4*)(q_hi + off) = make_uint4(ph[0], ph[1], ph[2], ph[3]);
        *(uint4*)(q_lo + off) = make_uint4(pl[0], pl[1], pl[2], pl[3]);
    } else {
        uint32_t p[4];
        #pragma unroll
        for (int i = 0; i < 4; i++) {
            __half2 t = __floats2half2_rn(f[2*i], f[2*i+1]);
            p[i] = *reinterpret_cast<uint32_t*>(&t);
        }
        __half* dst = (part == 1) ? k_h : v_h;
        *(uint4*)(dst + off) = make_uint4(p[0], p[1], p[2], p[3]);
    }
}

// ---------------------------------------------------------------------------
// Flash attention v4: Q hi/lo x K (2-term QK), P(hi only) x V (1-term PV).
// ---------------------------------------------------------------------------
__global__ __launch_bounds__(256) void fa_kernel(
    const __half* __restrict__ q_hi, const __half* __restrict__ q_lo,
    const __half* __restrict__ k_h, const __half* __restrict__ v_h,
    __half* __restrict__ o)
{
    extern __shared__ __align__(128) char sm[];
    uint32_t sb = smem_u32(sm);
    const uint32_t QHI = 0, QLO = 16384, STG = 32768;

    int tid = threadIdx.x, lane = tid & 31, wid = tid >> 5;
    int qt = blockIdx.x, h = blockIdx.y, b = blockIdx.z;
    size_t hb = (size_t)(b * HEADS + h) * NSEQ;

    {
        int arr = tid >> 7, r = tid & 127;
        const __half* src = (arr ? q_lo : q_hi) + (hb + qt * 128 + r) * DH;
        uint32_t dst = sb + (arr ? QLO : QHI);
        #pragma unroll
        for (int g = 0; g < 8; g++)
            cp_async16(dst + SWZ(r, g), src + g * 8);
        asm volatile("cp.async.commit_group;" ::: "memory");
    }
    int kvarr = tid >> 7, kvr = (tid >> 1) & 63, kvhalf = tid & 1;
    const __half* kvbase = (kvarr ? v_h : k_h) + hb * DH;
    #define LOAD_KV(buf, s0)                                                   \
    {                                                                          \
        uint32_t dst = sb + STG + (buf) * 16384 + kvarr * 8192;                \
        const __half* srcp = kvbase + ((size_t)(s0) + kvr) * DH + kvhalf * 32; \
        _Pragma("unroll")                                                      \
        for (int g = 0; g < 4; g++)                                            \
            cp_async16(dst + SWZ(kvr, kvhalf * 4 + g), srcp + g * 8);          \
        asm volatile("cp.async.commit_group;" ::: "memory");                   \
    }

    LOAD_KV(0, 0);
    asm volatile("cp.async.wait_group 1;" ::: "memory");
    __syncthreads();

    uint32_t qhi[4][4], qlo[4][4];
    #pragma unroll
    for (int kt = 0; kt < 4; kt++) {
        int rr = wid * 16 + ((lane >> 3) & 1) * 8 + (lane & 7);
        int gg = 2 * kt + (lane >> 4);
        ldsm4(qhi[kt], sb + QHI + SWZ(rr, gg));
        ldsm4(qlo[kt], sb + QLO + SWZ(rr, gg));
    }

    float accO[8][4];
    #pragma unroll
    for (int i = 0; i < 8; i++)
        #pragma unroll
        for (int j = 0; j < 4; j++) accO[i][j] = 0.f;
    float m0 = -1e30f, m1 = -1e30f, l0 = 0.f, l1 = 0.f;

    const int NT = NSEQ / 64;
    for (int kt = 0; kt < NT; kt++) {
        int cur = kt & 1;
        if (kt + 1 < NT) {
            LOAD_KV(1 - cur, (kt + 1) * 64);
            asm volatile("cp.async.wait_group 1;" ::: "memory");
        } else {
            asm volatile("cp.async.wait_group 0;" ::: "memory");
        }
        __syncthreads();
        uint32_t KS = sb + STG + cur * 16384;
        uint32_t VS = KS + 8192;

        // ---- S = (q_hi + q_lo) K^T
        float sAcc[8][4];
        #pragma unroll
        for (int i = 0; i < 8; i++)
            #pragma unroll
            for (int j = 0; j < 4; j++) sAcc[i][j] = 0.f;
        #pragma unroll
        for (int kk = 0; kk < 4; kk++) {
            #pragma unroll
            for (int g = 0; g < 4; g++) {
                uint32_t bh[4];
                int rr = g * 16 + ((lane >> 4) & 1) * 8 + (lane & 7);
                int cc = kk * 2 + ((lane >> 3) & 1);
                ldsm4(bh, KS + SWZ(rr, cc));
                mma16816(sAcc[2*g],   qhi[kk], bh[0], bh[1]);
                mma16816(sAcc[2*g+1], qhi[kk], bh[2], bh[3]);
                mma16816(sAcc[2*g],   qlo[kk], bh[0], bh[1]);
                mma16816(sAcc[2*g+1], qlo[kk], bh[2], bh[3]);
            }
        }

        // ---- online softmax
        float mx0 = -1e30f, mx1 = -1e30f;
        #pragma unroll
        for (int nt = 0; nt < 8; nt++) {
            mx0 = fmaxf(mx0, fmaxf(sAcc[nt][0], sAcc[nt][1]));
            mx1 = fmaxf(mx1, fmaxf(sAcc[nt][2], sAcc[nt][3]));
        }
        mx0 = fmaxf(mx0, __shfl_xor_sync(0xffffffffu, mx0, 1));
        mx0 = fmaxf(mx0, __shfl_xor_sync(0xffffffffu, mx0, 2));
        mx1 = fmaxf(mx1, __shfl_xor_sync(0xffffffffu, mx1, 1));
        mx1 = fmaxf(mx1, __shfl_xor_sync(0xffffffffu, mx1, 2));
        float mn0 = fmaxf(m0, mx0), mn1 = fmaxf(m1, mx1);
        float sc0 = exp2p(m0 - mn0), sc1 = exp2p(m1 - mn1);
        m0 = mn0; m1 = mn1;
        float rs0 = 0.f, rs1 = 0.f;
        #pragma unroll
        for (int nt = 0; nt < 8; nt++) {
            sAcc[nt][0] = exp2p(sAcc[nt][0] - m0); rs0 += sAcc[nt][0];
            sAcc[nt][1] = exp2p(sAcc[nt][1] - m0); rs0 += sAcc[nt][1];
            sAcc[nt][2] = exp2p(sAcc[nt][2] - m1); rs1 += sAcc[nt][2];
            sAcc[nt][3] = exp2p(sAcc[nt][3] - m1); rs1 += sAcc[nt][3];
        }
        rs0 += __shfl_xor_sync(0xffffffffu, rs0, 1);
        rs0 += __shfl_xor_sync(0xffffffffu, rs0, 2);
        rs1 += __shfl_xor_sync(0xffffffffu, rs1, 1);
        rs1 += __shfl_xor_sync(0xffffffffu, rs1, 2);
        l0 = l0 * sc0 + rs0;
        l1 = l1 * sc1 + rs1;
        #pragma unroll
        for (int dg = 0; dg < 8; dg++) {
            accO[dg][0] *= sc0; accO[dg][1] *= sc0;
            accO[dg][2] *= sc1; accO[dg][3] *= sc1;
        }

        // ---- P fragments (hi only)
        uint32_t phi[4][4];
        #pragma unroll
        for (int j = 0; j < 4; j++) {
            phi[j][0] = pack_h2(__float2half_rn(sAcc[2*j][0]),   __float2half_rn(sAcc[2*j][1]));
            phi[j][1] = pack_h2(__float2half_rn(sAcc[2*j][2]),   __float2half_rn(sAcc[2*j][3]));
            phi[j][2] = pack_h2(__float2half_rn(sAcc[2*j+1][0]), __float2half_rn(sAcc[2*j+1][1]));
            phi[j][3] = pack_h2(__float2half_rn(sAcc[2*j+1][2]), __float2half_rn(sAcc[2*j+1][3]));
        }

        // ---- O += P V (single term)
        #pragma unroll
        for (int j = 0; j < 4; j++) {
            #pragma unroll
            for (int dgp = 0; dgp < 4; dgp++) {
                uint32_t vh[4];
                int rr = j * 16 + ((lane >> 3) & 1) * 8 + (lane & 7);
                int cc = dgp * 2 + (lane >> 4);
                ldsm4t(vh, VS + SWZ(rr, cc));
                mma16816(accO[2*dgp],   phi[j], vh[0], vh[1]);
                mma16816(accO[2*dgp+1], phi[j], vh[2], vh[3]);
            }
        }
        __syncthreads();
    }

    float inv0 = 1.f / l0, inv1 = 1.f / l1;
    int row = b * NSEQ + qt * 128 + wid * 16 + (lane >> 2);
    __half* op0 = o + (size_t)row * INNER + h * DH + 2 * (lane & 3);
    __half* op1 = op0 + (size_t)8 * INNER;
    #pragma unroll
    for (int dg = 0; dg < 8; dg++) {
        *(__half2*)(op0 + dg * 8) = __floats2half2_rn(accO[dg][0] * inv0, accO[dg][1] * inv0);
        *(__half2*)(op1 + dg * 8) = __floats2half2_rn(accO[dg][2] * inv1, accO[dg][3] * inv1);
    }
}

// ---------------------------------------------------------------------------
extern "C" void kernel_launch(void* const* d_in, const int* in_sizes, int n_in,
                              void* d_out, int out_size)
{
    const float* x     = (const float*)d_in[0];
    const float* ln_g  = (const float*)d_in[1];
    const float* ln_b  = (const float*)d_in[2];
    const float* w_qkv = (const float*)d_in[3];
    const float* w_out = (const float*)d_in[4];
    const float* b_out = (const float*)d_in[5];
    float* out = (float*)d_out;

    __half *xn_h, *o_h, *wqkvT_h, *woutT_h;
    __half *q_hi, *q_lo, *k_h, *v_h;
    float *qkv, *cosT, *sinT;
    cudaGetSymbolAddress((void**)&xn_h,    g_xn_h);
    cudaGetSymbolAddress((void**)&qkv,     g_qkv);
    cudaGetSymbolAddress((void**)&o_h,     g_o_h);
    cudaGetSymbolAddress((void**)&wqkvT_h, g_wqkvT_h);
    cudaGetSymbolAddress((void**)&woutT_h, g_woutT_h);
    cudaGetSymbolAddress((void**)&cosT,    g_cosT);
    cudaGetSymbolAddress((void**)&sinT,    g_sinT);
    cudaGetSymbolAddress((void**)&q_hi,    g_q_hi);
    cudaGetSymbolAddress((void**)&q_lo,    g_q_lo);
    cudaGetSymbolAddress((void**)&k_h,     g_k_h);
    cudaGetSymbolAddress((void**)&v_h,     g_v_h);

    static int cfg_done = 0;
    if (!cfg_done) {
        cudaFuncSetAttribute(fa_kernel, cudaFuncAttributeMaxDynamicSharedMemorySize, 65536);
        cfg_done = 1;
    }

    ln_kernel<<<ROWS, 256>>>(x, ln_g, ln_b, xn_h);
    transpose_cvt_kernel<<<dim3(NQKV / 32, DIM / 32), 256>>>(w_qkv, wqkvT_h, DIM, NQKV);
    transpose_cvt_kernel<<<dim3(DIM / 32, INNER / 32), 256>>>(w_out, woutT_h, INNER, DIM);
    rope_table_kernel<<<(NSEQ * DH) / 256, 256>>>(cosT, sinT);

    hgemm<<<dim3(NQKV / 128, ROWS / 128), 256>>>(
        xn_h, wqkvT_h, nullptr, qkv, ROWS, NQKV, DIM, 0);

    rope_cvt_kernel<<<ROWS, 384>>>(qkv, cosT, sinT, q_hi, q_lo, k_h, v_h);

    fa_kernel<<<dim3(NSEQ / 128, HEADS, BATCH), 256, 65536>>>(
        q_hi, q_lo, k_h, v_h, o_h);

    hgemm<<<dim3(DIM / 128, ROWS / 128), 256>>>(
        o_h, woutT_h, b_out, out, ROWS, DIM, INNER, 1);
}